// round 11
// baseline (speedup 1.0000x reference)
#include <cuda_runtime.h>
#include <cuda_bf16.h>
#include <cstdint>

// Per molecule: S = 32x128 fp32, C = S S^T (32x32), output lambda_min(C).
// One warp per molecule:
//   1) Gram via cp.async-staged 32x32 chunks; broadcast-row inner loop
//      (1-wavefront LDS) + packed f32x2 FMA.
//   2) Householder tridiagonalization, A-row in registers; column k read from
//      the lane's own row by symmetry (fully unrolled -> const reg index).
//   3) lambda_min via 32-way multisection on the Sturm sequence (4 rounds).

#define NA 32
#define NF 128
#define WPB 4   // warps (=molecules) per block

typedef unsigned long long u64;

__device__ __forceinline__ u64 pk2(float x, float y) {
    u64 r; asm("mov.b64 %0, {%1,%2};" : "=l"(r) : "f"(x), "f"(y)); return r;
}
__device__ __forceinline__ void upk2(u64 v, float& x, float& y) {
    asm("mov.b64 {%0,%1}, %2;" : "=f"(x), "=f"(y) : "l"(v));
}
__device__ __forceinline__ u64 ffma2(u64 a, u64 b, u64 c) {
    u64 d; asm("fma.rn.f32x2 %0, %1, %2, %3;" : "=l"(d) : "l"(a), "l"(b), "l"(c)); return d;
}
__device__ __forceinline__ u64 fadd2(u64 a, u64 b) {
    u64 d; asm("add.rn.f32x2 %0, %1, %2;" : "=l"(d) : "l"(a), "l"(b)); return d;
}
__device__ __forceinline__ void lds_v2u64(uint32_t addr, u64& a, u64& b) {
    asm("ld.shared.v2.b64 {%0,%1}, [%2];" : "=l"(a), "=l"(b) : "r"(addr));
}
__device__ __forceinline__ u64 lds_u64(uint32_t addr) {
    u64 a; asm("ld.shared.b64 %0, [%1];" : "=l"(a) : "r"(addr)); return a;
}
__device__ __forceinline__ void cp16(uint32_t dst, const void* src) {
    asm volatile("cp.async.ca.shared.global [%0], [%1], 16;" :: "r"(dst), "l"(src) : "memory");
}

__global__ void __launch_bounds__(32 * WPB, 6)
corr_minEig_kernel(const float* __restrict__ S, float* __restrict__ out, int mtot) {
    __shared__ __align__(16) float sS[WPB][NA * 36];   // 32x32 chunk staging, stride 36
    __shared__ __align__(16) float sv[WPB][NA];        // Householder v
    __shared__ __align__(16) float sw[WPB][NA];        // Householder w
    __shared__ float sd[WPB][NA];                      // tridiagonal diag
    __shared__ float se2[WPB][NA];                     // tridiagonal offdiag^2

    const int w    = threadIdx.x >> 5;
    const int lane = threadIdx.x & 31;
    const int mol  = blockIdx.x * WPB + w;
    if (mol >= mtot) return;

    const float* Sm = S + (size_t)mol * NA * NF;
    const uint32_t sS_base = (uint32_t)__cvta_generic_to_shared(&sS[w][0]);
    const uint32_t v_base  = (uint32_t)__cvta_generic_to_shared(&sv[w][0]);
    const uint32_t w_base  = (uint32_t)__cvta_generic_to_shared(&sw[w][0]);
    float* d  = sd[w];
    float* e2 = se2[w];

    // ------------------------------------------------------------------
    // 1) Gram: acc[j] = dot(row lane, row j); broadcast rows = 1-wf LDS
    // ------------------------------------------------------------------
    float acc[NA];
#pragma unroll
    for (int j = 0; j < NA; j++) acc[j] = 0.f;

    for (int kc = 0; kc < NF; kc += 32) {
        // stage 32x32 chunk via cp.async (coalesced 128B segments)
#pragma unroll
        for (int it = 0; it < 8; it++) {
            int p   = it * 32 + lane;
            int row = p >> 3;
            int c4  = p & 7;
            cp16(sS_base + (uint32_t)(row * 36 + c4 * 4) * 4,
                 Sm + row * NF + kc + c4 * 4);
        }
        asm volatile("cp.async.commit_group;" ::: "memory");
        asm volatile("cp.async.wait_group 0;" ::: "memory");
        __syncwarp();

        // own row chunk -> 16 packed b64 (conflict-free: stride-36 rows)
        u64 a2[16];
#pragma unroll
        for (int c4 = 0; c4 < 8; c4++)
            lds_v2u64(sS_base + (uint32_t)(lane * 36 + c4 * 4) * 4, a2[2 * c4], a2[2 * c4 + 1]);

        // accumulate against broadcast row j (all lanes same addr -> 1 wf)
#pragma unroll
        for (int j = 0; j < NA; j++) {
            uint32_t raddr = sS_base + (uint32_t)j * 144u;
            u64 s01 = 0, s23 = 0;
#pragma unroll
            for (int c4 = 0; c4 < 8; c4++) {
                u64 b01, b23;
                lds_v2u64(raddr + c4 * 16u, b01, b23);
                s01 = ffma2(a2[2 * c4],     b01, s01);
                s23 = ffma2(a2[2 * c4 + 1], b23, s23);
            }
            float lo, hi; upk2(fadd2(s01, s23), lo, hi);
            acc[j] += lo + hi;
        }
        __syncwarp();
    }

    // pack A row (lane owns row `lane` of C) into 16 b64 registers
    u64 arow[16];
#pragma unroll
    for (int i = 0; i < 16; i++) arow[i] = pk2(acc[2 * i], acc[2 * i + 1]);

    // ------------------------------------------------------------------
    // 2) Householder tridiagonalization, fully unrolled over k.
    //    Column k == element k of the lane's own row (symmetry).
    // ------------------------------------------------------------------
#pragma unroll
    for (int k = 0; k < NA - 2; k++) {
        const int i0 = k >> 1;      // first pair touching columns > k-1

        float ea, eb; upk2(arow[k >> 1], ea, eb);
        float xr = (k & 1) ? eb : ea;                    // A[lane][k] == A[k][lane]
        float dk = __shfl_sync(0xffffffffu, xr, k);      // A[k][k]
        float x0 = __shfl_sync(0xffffffffu, xr, k + 1);  // A[k][k+1]
        float sig = (lane > k + 1) ? xr * xr : 0.f;
#pragma unroll
        for (int o = 16; o; o >>= 1) sig += __shfl_xor_sync(0xffffffffu, sig, o);

        float alpha, vr = 0.f, beta = 0.f;
        if (sig < 1e-30f) {
            alpha = x0;
        } else {
            float mu = sqrtf(x0 * x0 + sig);
            alpha = (x0 > 0.f) ? -mu : mu;
            float v0 = x0 - alpha;
            vr = (lane == k + 1) ? v0 : ((lane > k + 1) ? xr : 0.f);
            beta = 2.f / (v0 * v0 + sig);
        }
        if (lane == 0) { d[k] = dk; e2[k + 1] = alpha * alpha; }
        sv[w][lane] = vr;                                // zero for lane <= k
        __syncwarp();

        if (beta > 0.f) {                                // uniform branch
            // p = beta * A v  (v zero-padded below k+1); 2-way ILP split
            u64 p2a = 0, p2b = 0;
#pragma unroll
            for (int i = i0; i < 16; i += 2)
                p2a = ffma2(arow[i], lds_u64(v_base + i * 8), p2a);
#pragma unroll
            for (int i = i0 + 1; i < 16; i += 2)
                p2b = ffma2(arow[i], lds_u64(v_base + i * 8), p2b);
            float plo, phi; upk2(fadd2(p2a, p2b), plo, phi);
            float p = (plo + phi) * beta;

            float pv = p * vr;                           // vr=0 for lane<=k
#pragma unroll
            for (int o = 16; o; o >>= 1) pv += __shfl_xor_sync(0xffffffffu, pv, o);
            float K  = 0.5f * beta * pv;
            float wr = (lane > k) ? (p - K * vr) : 0.f;
            sw[w][lane] = wr;
            __syncwarp();

            // A -= v w^T + w v^T (untouched pairs below i0 skipped)
            u64 nv = pk2(-vr, -vr);
            u64 nw = pk2(-wr, -wr);
#pragma unroll
            for (int i = i0; i < 16; i++) {
                u64 v2 = lds_u64(v_base + i * 8);
                u64 w2 = lds_u64(w_base + i * 8);
                arow[i] = ffma2(nv, w2, ffma2(nw, v2, arow[i]));
            }
        }
        __syncwarp();
    }

    if (lane == NA - 2) {                 // row 30: pair 15 = (A[30][30], A[30][31])
        float a, b; upk2(arow[15], a, b);
        d[NA - 2] = a;
    }
    if (lane == NA - 1) {                 // row 31: pair 15 = (A[31][30], A[31][31])
        float a, b; upk2(arow[15], a, b);
        d[NA - 1] = b;
        e2[NA - 1] = a * a;
    }
    if (lane == 0) e2[0] = 0.f;
    __syncwarp();

    // ------------------------------------------------------------------
    // 3) lambda_min: Gershgorin bracket + 32-way multisection (Sturm count)
    // ------------------------------------------------------------------
    float ei  = sqrtf(e2[lane]);
    float eip = (lane < NA - 1) ? sqrtf(e2[lane + 1]) : 0.f;
    float rad = ei + eip;
    float dl  = d[lane];
    float lo = dl - rad, hi = dl + rad;
#pragma unroll
    for (int o = 16; o; o >>= 1) {
        lo = fminf(lo, __shfl_xor_sync(0xffffffffu, lo, o));
        hi = fmaxf(hi, __shfl_xor_sync(0xffffffffu, hi, o));
    }

    for (int it = 0; it < 4; it++) {
        float step = (hi - lo) * (1.f / 33.f);
        float x = lo + step * (float)(lane + 1);
        int cnt = 0;
        float q = d[0] - x;
        if (q < 0.f) cnt++;
#pragma unroll
        for (int i = 1; i < NA; i++) {
            if (fabsf(q) < 1e-25f) q = (q < 0.f) ? -1e-25f : 1e-25f;
            q = (d[i] - x) - __fdividef(e2[i], q);
            if (q < 0.f) cnt++;
        }
        unsigned mask = __ballot_sync(0xffffffffu, cnt >= 1);
        if (mask == 0u) {
            lo = lo + step * 32.f;
        } else {
            int idx = __ffs(mask) - 1;
            hi = lo + step * (float)(idx + 1);
            lo = lo + step * (float)idx;
        }
    }

    if (lane == 0) out[mol] = 0.5f * (lo + hi);
}

extern "C" void kernel_launch(void* const* d_in, const int* in_sizes, int n_in,
                              void* d_out, int out_size) {
    const float* sr = (const float*)d_in[0];   // [M*32, 128] fp32
    // d_in[1] = idx_m (int32) — uniform groups, unused
    float* out = (float*)d_out;

    int n_atoms = in_sizes[0] / NF;
    int mtot    = n_atoms / NA;

    int blocks = (mtot + WPB - 1) / WPB;
    corr_minEig_kernel<<<blocks, 32 * WPB>>>(sr, out, mtot);
}